// round 1
// baseline (speedup 1.0000x reference)
#include <cuda_runtime.h>
#include <cstdint>

// Problem constants (fixed by the benchmark)
#define T_TOK 8192
#define DDIM  4096
#define ODIM  4096
#define LMAX  8
#define RANK  16

// Scratch for LoRA shrink result s[T, R]  (512 KB static device array — no allocs)
__device__ float g_s[T_TOK * RANK];

// ---------------------------------------------------------------------------
// Packed f32x2 helpers (Blackwell): one instruction = 2 fp32 FMAs
// ---------------------------------------------------------------------------
__device__ __forceinline__ unsigned long long bcast2(float x) {
    unsigned long long r;
    unsigned int xi = __float_as_uint(x);
    asm("mov.b64 %0, {%1, %1};" : "=l"(r) : "r"(xi));
    return r;
}
__device__ __forceinline__ void fma2(unsigned long long& d,
                                     unsigned long long a,
                                     unsigned long long b) {
    asm("fma.rn.f32x2 %0, %1, %2, %3;" : "=l"(d) : "l"(a), "l"(b), "l"(d));
}

// ---------------------------------------------------------------------------
// Kernel 1: LoRA shrink.  s[t, r] = sum_d x[t,d] * lora_a[idx[t], r, d]
// One block per token, 128 threads, block-wide reduction.
// ---------------------------------------------------------------------------
__global__ void lora_shrink(const float* __restrict__ x,
                            const float* __restrict__ la,
                            const int*   __restrict__ idx) {
    const int t = blockIdx.x;
    const int l = idx[t];
    const float4* xt = reinterpret_cast<const float4*>(x + (size_t)t * DDIM);
    const float4* A  = reinterpret_cast<const float4*>(la + (size_t)l * RANK * DDIM);
    const int D4 = DDIM / 4;

    float acc[RANK];
#pragma unroll
    for (int r = 0; r < RANK; r++) acc[r] = 0.f;

    for (int i = threadIdx.x; i < D4; i += 128) {
        float4 xv = xt[i];
#pragma unroll
        for (int r = 0; r < RANK; r++) {
            float4 av = A[r * D4 + i];
            acc[r] += xv.x * av.x + xv.y * av.y + xv.z * av.z + xv.w * av.w;
        }
    }

    __shared__ float red[RANK][128];
#pragma unroll
    for (int r = 0; r < RANK; r++) red[r][threadIdx.x] = acc[r];
    __syncthreads();

    for (int off = 64; off > 0; off >>= 1) {
        if (threadIdx.x < off) {
#pragma unroll
            for (int r = 0; r < RANK; r++)
                red[r][threadIdx.x] += red[r][threadIdx.x + off];
        }
        __syncthreads();
    }
    if (threadIdx.x < RANK)
        g_s[t * RANK + threadIdx.x] = red[threadIdx.x][0];
}

// ---------------------------------------------------------------------------
// Kernel 2: base GEMM.  C[m,n] = sum_k A[m,k] * B[n,k]
// A = x [T, D] row-major, B = weight [O, D] row-major (both K-major, "NT").
// 128x128 tile, BK=16, 256 threads, 8x8 per-thread micro-tile, f32x2 FMAs,
// register-staged global prefetch.
// ---------------------------------------------------------------------------
#define BM 128
#define BN 128
#define BK 16

__global__ __launch_bounds__(256, 2)
void base_gemm(const float* __restrict__ A,
               const float* __restrict__ B,
               float* __restrict__ C) {
    __shared__ float As[BK][BM];
    __shared__ float Bs[BK][BN];

    const int tid = threadIdx.x;
    const int bm = blockIdx.y * BM;
    const int bn = blockIdx.x * BN;

    // Loader mapping: 256 threads, each loads 2 float4 of A and 2 of B per k-tile
    const int ldrow = tid >> 2;          // 0..63
    const int ldk   = (tid & 3) << 2;    // 0,4,8,12

    const float* Ag = A + (size_t)(bm + ldrow) * DDIM + ldk;
    const float* Bg = B + (size_t)(bn + ldrow) * DDIM + ldk;

    // Compute mapping: 16x16 thread grid, each thread owns 8 rows x 8 cols
    const int ty = tid >> 4;   // 0..15
    const int tx = tid & 15;   // 0..15

    unsigned long long acc[8][4];
#pragma unroll
    for (int i = 0; i < 8; i++)
#pragma unroll
        for (int j = 0; j < 4; j++) acc[i][j] = 0ull;

    // Initial staged loads (k0 = 0)
    float4 a0 = *reinterpret_cast<const float4*>(Ag);
    float4 a1 = *reinterpret_cast<const float4*>(Ag + (size_t)64 * DDIM);
    float4 b0 = *reinterpret_cast<const float4*>(Bg);
    float4 b1 = *reinterpret_cast<const float4*>(Bg + (size_t)64 * DDIM);

    for (int k0 = 0; k0 < DDIM; k0 += BK) {
        // Commit staged registers to shared (transposed: As[k][m])
        As[ldk + 0][ldrow]      = a0.x;
        As[ldk + 1][ldrow]      = a0.y;
        As[ldk + 2][ldrow]      = a0.z;
        As[ldk + 3][ldrow]      = a0.w;
        As[ldk + 0][ldrow + 64] = a1.x;
        As[ldk + 1][ldrow + 64] = a1.y;
        As[ldk + 2][ldrow + 64] = a1.z;
        As[ldk + 3][ldrow + 64] = a1.w;
        Bs[ldk + 0][ldrow]      = b0.x;
        Bs[ldk + 1][ldrow]      = b0.y;
        Bs[ldk + 2][ldrow]      = b0.z;
        Bs[ldk + 3][ldrow]      = b0.w;
        Bs[ldk + 0][ldrow + 64] = b1.x;
        Bs[ldk + 1][ldrow + 64] = b1.y;
        Bs[ldk + 2][ldrow + 64] = b1.z;
        Bs[ldk + 3][ldrow + 64] = b1.w;
        __syncthreads();

        // Prefetch next k-tile while computing on this one
        if (k0 + BK < DDIM) {
            a0 = *reinterpret_cast<const float4*>(Ag + k0 + BK);
            a1 = *reinterpret_cast<const float4*>(Ag + (size_t)64 * DDIM + k0 + BK);
            b0 = *reinterpret_cast<const float4*>(Bg + k0 + BK);
            b1 = *reinterpret_cast<const float4*>(Bg + (size_t)64 * DDIM + k0 + BK);
        }

#pragma unroll
        for (int kk = 0; kk < BK; kk++) {
            const float4* arow = reinterpret_cast<const float4*>(&As[kk][ty * 8]);
            float4 af0 = arow[0];
            float4 af1 = arow[1];
            float a[8] = {af0.x, af0.y, af0.z, af0.w, af1.x, af1.y, af1.z, af1.w};

            const unsigned long long* brow =
                reinterpret_cast<const unsigned long long*>(&Bs[kk][tx * 8]);
            unsigned long long bv[4];
#pragma unroll
            for (int j = 0; j < 4; j++) bv[j] = brow[j];

#pragma unroll
            for (int i = 0; i < 8; i++) {
                unsigned long long av = bcast2(a[i]);
#pragma unroll
                for (int j = 0; j < 4; j++) fma2(acc[i][j], av, bv[j]);
            }
        }
        __syncthreads();
    }

    // Epilogue: unpack f32x2 accumulators and store (each row = 2 float4)
#pragma unroll
    for (int i = 0; i < 8; i++) {
        float4 v0, v1;
        v0.x = __uint_as_float((unsigned)(acc[i][0] & 0xffffffffull));
        v0.y = __uint_as_float((unsigned)(acc[i][0] >> 32));
        v0.z = __uint_as_float((unsigned)(acc[i][1] & 0xffffffffull));
        v0.w = __uint_as_float((unsigned)(acc[i][1] >> 32));
        v1.x = __uint_as_float((unsigned)(acc[i][2] & 0xffffffffull));
        v1.y = __uint_as_float((unsigned)(acc[i][2] >> 32));
        v1.z = __uint_as_float((unsigned)(acc[i][3] & 0xffffffffull));
        v1.w = __uint_as_float((unsigned)(acc[i][3] >> 32));
        float* crow = C + (size_t)(bm + ty * 8 + i) * ODIM + bn + tx * 8;
        *reinterpret_cast<float4*>(crow)     = v0;
        *reinterpret_cast<float4*>(crow + 4) = v1;
    }
}

// ---------------------------------------------------------------------------
// Kernel 3: LoRA expand.  out[t,o] += sum_r s[t,r] * lora_b[idx[t], o, r]
// One block row per token, 256 outputs per block; lora_b row = 64B (4 float4).
// ---------------------------------------------------------------------------
__global__ void lora_expand(const float* __restrict__ lb,
                            const int*   __restrict__ idx,
                            float* __restrict__ out) {
    const int t = blockIdx.y;
    const int o = blockIdx.x * blockDim.x + threadIdx.x;

    __shared__ float ss[RANK];
    __shared__ int   sl;
    if (threadIdx.x < RANK) ss[threadIdx.x] = g_s[t * RANK + threadIdx.x];
    if (threadIdx.x == 0)   sl = idx[t];
    __syncthreads();

    const float4* Brow =
        reinterpret_cast<const float4*>(lb + ((size_t)sl * ODIM + o) * RANK);
    float acc = 0.f;
#pragma unroll
    for (int i = 0; i < 4; i++) {
        float4 b = Brow[i];
        acc += b.x * ss[4 * i + 0] + b.y * ss[4 * i + 1] +
               b.z * ss[4 * i + 2] + b.w * ss[4 * i + 3];
    }
    out[(size_t)t * ODIM + o] += acc;
}

// ---------------------------------------------------------------------------
// Launch: inputs per metadata order: x, weight, lora_a, lora_b, token_lora_idx
// ---------------------------------------------------------------------------
extern "C" void kernel_launch(void* const* d_in, const int* in_sizes, int n_in,
                              void* d_out, int out_size) {
    const float* x   = (const float*)d_in[0];
    const float* w   = (const float*)d_in[1];
    const float* la  = (const float*)d_in[2];
    const float* lb  = (const float*)d_in[3];
    const int*   idx = (const int*)d_in[4];
    float* out = (float*)d_out;

    // 1) shrink: s[t, r]
    lora_shrink<<<T_TOK, 128>>>(x, la, idx);

    // 2) base GEMM: out = x @ W^T
    dim3 ggrid(ODIM / BN, T_TOK / BM);
    base_gemm<<<ggrid, 256>>>(x, w, out);

    // 3) expand: out += delta
    dim3 egrid(ODIM / 256, T_TOK);
    lora_expand<<<egrid, 256>>>(lb, idx, out);
}

// round 3
// speedup vs baseline: 2.4504x; 2.4504x over previous
#include <cuda_runtime.h>
#include <cuda_bf16.h>
#include <cstdint>

// Problem constants
#define T_TOK 8192
#define DDIM  4096
#define ODIM  4096
#define LMAX  8
#define RANK  16

// ---------------------------------------------------------------------------
// Static device scratch (no allocations allowed)
// ---------------------------------------------------------------------------
__device__ float g_s[T_TOK * RANK];                      // LoRA shrink result
__device__ __nv_bfloat16 g_xhi[(size_t)T_TOK * DDIM];    // 64 MB
__device__ __nv_bfloat16 g_xlo[(size_t)T_TOK * DDIM];    // 64 MB
__device__ __nv_bfloat16 g_whi[(size_t)ODIM * DDIM];     // 32 MB
__device__ __nv_bfloat16 g_wlo[(size_t)ODIM * DDIM];     // 32 MB

// ---------------------------------------------------------------------------
// PTX helpers (all sm_80/90-era: legal on plain sm_103 target)
// ---------------------------------------------------------------------------
__device__ __forceinline__ uint32_t smem_u32(const void* p) {
    uint32_t a;
    asm("{ .reg .u64 t; cvta.to.shared.u64 t, %1; cvt.u32.u64 %0, t; }"
        : "=r"(a) : "l"(p));
    return a;
}
__device__ __forceinline__ void cp16(uint32_t d, const void* g) {
    asm volatile("cp.async.cg.shared.global [%0], [%1], 16;"
                 :: "r"(d), "l"(g) : "memory");
}
__device__ __forceinline__ void ldsm4(uint32_t* r, uint32_t a) {
    asm volatile("ldmatrix.sync.aligned.m8n8.x4.shared.b16 {%0,%1,%2,%3}, [%4];"
                 : "=r"(r[0]), "=r"(r[1]), "=r"(r[2]), "=r"(r[3]) : "r"(a));
}
__device__ __forceinline__ void mma_bf16(float* c, const uint32_t* a,
                                         uint32_t b0, uint32_t b1) {
    asm volatile(
        "mma.sync.aligned.m16n8k16.row.col.f32.bf16.bf16.f32 "
        "{%0,%1,%2,%3}, {%4,%5,%6,%7}, {%8,%9}, {%0,%1,%2,%3};"
        : "+f"(c[0]), "+f"(c[1]), "+f"(c[2]), "+f"(c[3])
        : "r"(a[0]), "r"(a[1]), "r"(a[2]), "r"(a[3]), "r"(b0), "r"(b1));
}

// ---------------------------------------------------------------------------
// fp32 -> (hi, lo) bf16 split kernels
// ---------------------------------------------------------------------------
__global__ void split_x(const float* __restrict__ in) {
    size_t n4 = (size_t)T_TOK * DDIM / 4;
    const float4* in4 = reinterpret_cast<const float4*>(in);
    for (size_t i = blockIdx.x * blockDim.x + threadIdx.x; i < n4;
         i += (size_t)gridDim.x * blockDim.x) {
        float4 v = in4[i];
        __nv_bfloat16 h0 = __float2bfloat16(v.x), h1 = __float2bfloat16(v.y);
        __nv_bfloat16 h2 = __float2bfloat16(v.z), h3 = __float2bfloat16(v.w);
        __nv_bfloat162 hi0{h0, h1}, hi1{h2, h3};
        __nv_bfloat162 lo0{__float2bfloat16(v.x - __bfloat162float(h0)),
                           __float2bfloat16(v.y - __bfloat162float(h1))};
        __nv_bfloat162 lo1{__float2bfloat16(v.z - __bfloat162float(h2)),
                           __float2bfloat16(v.w - __bfloat162float(h3))};
        reinterpret_cast<__nv_bfloat162*>(g_xhi)[i * 2]     = hi0;
        reinterpret_cast<__nv_bfloat162*>(g_xhi)[i * 2 + 1] = hi1;
        reinterpret_cast<__nv_bfloat162*>(g_xlo)[i * 2]     = lo0;
        reinterpret_cast<__nv_bfloat162*>(g_xlo)[i * 2 + 1] = lo1;
    }
}
__global__ void split_w(const float* __restrict__ in) {
    size_t n4 = (size_t)ODIM * DDIM / 4;
    const float4* in4 = reinterpret_cast<const float4*>(in);
    for (size_t i = blockIdx.x * blockDim.x + threadIdx.x; i < n4;
         i += (size_t)gridDim.x * blockDim.x) {
        float4 v = in4[i];
        __nv_bfloat16 h0 = __float2bfloat16(v.x), h1 = __float2bfloat16(v.y);
        __nv_bfloat16 h2 = __float2bfloat16(v.z), h3 = __float2bfloat16(v.w);
        __nv_bfloat162 hi0{h0, h1}, hi1{h2, h3};
        __nv_bfloat162 lo0{__float2bfloat16(v.x - __bfloat162float(h0)),
                           __float2bfloat16(v.y - __bfloat162float(h1))};
        __nv_bfloat162 lo1{__float2bfloat16(v.z - __bfloat162float(h2)),
                           __float2bfloat16(v.w - __bfloat162float(h3))};
        reinterpret_cast<__nv_bfloat162*>(g_whi)[i * 2]     = hi0;
        reinterpret_cast<__nv_bfloat162*>(g_whi)[i * 2 + 1] = hi1;
        reinterpret_cast<__nv_bfloat162*>(g_wlo)[i * 2]     = lo0;
        reinterpret_cast<__nv_bfloat162*>(g_wlo)[i * 2 + 1] = lo1;
    }
}

// ---------------------------------------------------------------------------
// GEMM via mma.sync (bf16 x3 hi/lo products, fp32 accumulate)
// 128x128 tile, BK=32, 4-stage cp.async pipeline, 8 warps (64x32 warp tiles).
// SMEM layout per stage: [Ahi|Alo|Bhi|Blo], each 128 rows x 64B,
// 16B chunks XOR-swizzled: phys_chunk = c ^ ((row>>1)&3).
// ---------------------------------------------------------------------------
#define BKC     32
#define NCHUNKC (DDIM / BKC)
#define TILEB   (128 * 64)          // 8 KB
#define STAGEB  (4 * TILEB)         // 32 KB
#define STAGES  4
#define GEMM_SMEM (STAGES * STAGEB) // 128 KB

__global__ __launch_bounds__(256, 1)
void gemm_mma(float* __restrict__ C) {
    extern __shared__ char smem[];
    const uint32_t sb = smem_u32(smem);
    const int tid  = threadIdx.x;
    const int wid  = tid >> 5;
    const int lane = tid & 31;

    // Rasterize: GROUP_M=8 super-rows so a wave's working set fits L2
    const int bid = blockIdx.x;
    const int TN = ODIM / 128;                 // 32
    const int GRP = 8;
    const int per = GRP * TN;
    const int m_t = (bid / per) * GRP + (bid % per) % GRP;
    const int n_t = (bid % per) / GRP;
    const int bm = m_t * 128;
    const int bn = n_t * 128;

    const int warp_m = wid & 1;   // 2 x 64 rows
    const int warp_n = wid >> 1;  // 4 x 32 cols

    // -------- async loader --------
    auto issue_chunk = [&](int chunk, int stage) {
        const int k0 = chunk * BKC;
        const uint32_t sbase = sb + (uint32_t)stage * STAGEB;
#pragma unroll
        for (int t = 0; t < 4; t++) {
            const __nv_bfloat16* src =
                (t == 0) ? g_xhi : (t == 1) ? g_xlo : (t == 2) ? g_whi : g_wlo;
            const int row0 = (t < 2) ? bm : bn;
#pragma unroll
            for (int rep = 0; rep < 2; rep++) {
                const int idx = rep * 256 + tid;     // 0..511
                const int r = idx >> 2;              // 0..127
                const int c = idx & 3;               // chunk 0..3
                const void* g = src + (size_t)(row0 + r) * DDIM + k0 + c * 8;
                const uint32_t d = sbase + (uint32_t)t * TILEB + r * 64 +
                                   ((c ^ ((r >> 1) & 3)) << 4);
                cp16(d, g);
            }
        }
        asm volatile("cp.async.commit_group;" ::: "memory");
    };

    float acc[4][4][4];
#pragma unroll
    for (int i = 0; i < 4; i++)
#pragma unroll
        for (int j = 0; j < 4; j++)
#pragma unroll
            for (int q = 0; q < 4; q++) acc[i][j][q] = 0.f;

    // Prologue: fill STAGES-1 stages
#pragma unroll
    for (int s = 0; s < STAGES - 1; s++) issue_chunk(s, s);

    // A ldmatrix lane mapping: row = lane%16 (m), half = lane/16
    const int a_r = lane & 15;
    const int a_h = lane >> 4;
    // B ldmatrix lane mapping: row = (lane%8) + (lane/16)*8 (n), half = (lane>>3)&1
    const int b_r = (lane & 7) + ((lane >> 4) << 3);
    const int b_h = (lane >> 3) & 1;

    for (int i = 0; i < NCHUNKC; i++) {
        const int stage = i % STAGES;
        asm volatile("cp.async.wait_group %0;" :: "n"(STAGES - 2) : "memory");
        __syncthreads();
        if (i + STAGES - 1 < NCHUNKC)
            issue_chunk(i + STAGES - 1, (i + STAGES - 1) % STAGES);

        const uint32_t st = sb + (uint32_t)stage * STAGEB;
        const uint32_t Ah = st, Al = st + TILEB, Bh = st + 2 * TILEB, Bl = st + 3 * TILEB;

#pragma unroll
        for (int ks = 0; ks < 2; ks++) {
            uint32_t ahi[4][4], alo[4][4], bhi[2][4], blo[2][4];
#pragma unroll
            for (int mt = 0; mt < 4; mt++) {
                const int row = warp_m * 64 + mt * 16 + a_r;
                const int cl = ks * 2 + a_h;
                const uint32_t off = row * 64 + ((cl ^ ((row >> 1) & 3)) << 4);
                ldsm4(ahi[mt], Ah + off);
                ldsm4(alo[mt], Al + off);
            }
#pragma unroll
            for (int p = 0; p < 2; p++) {
                const int row = warp_n * 32 + p * 16 + b_r;
                const int cl = ks * 2 + b_h;
                const uint32_t off = row * 64 + ((cl ^ ((row >> 1) & 3)) << 4);
                ldsm4(bhi[p], Bh + off);
                ldsm4(blo[p], Bl + off);
            }
            // bhi[p] regs: {r0,r1} = n-tile 2p (b0,b1); {r2,r3} = n-tile 2p+1
#pragma unroll
            for (int mt = 0; mt < 4; mt++) {
#pragma unroll
                for (int nt = 0; nt < 4; nt++) {
                    const uint32_t bh0 = bhi[nt >> 1][(nt & 1) * 2];
                    const uint32_t bh1 = bhi[nt >> 1][(nt & 1) * 2 + 1];
                    const uint32_t bl0 = blo[nt >> 1][(nt & 1) * 2];
                    const uint32_t bl1 = blo[nt >> 1][(nt & 1) * 2 + 1];
                    mma_bf16(acc[mt][nt], ahi[mt], bh0, bh1);  // hi*hi
                    mma_bf16(acc[mt][nt], alo[mt], bh0, bh1);  // lo*hi
                    mma_bf16(acc[mt][nt], ahi[mt], bl0, bl1);  // hi*lo
                }
            }
        }
    }

    // Epilogue: c frag layout: rows lane/4 (+8), cols (lane%4)*2 (+1)
    const int er = lane >> 2;
    const int ec = (lane & 3) * 2;
#pragma unroll
    for (int mt = 0; mt < 4; mt++) {
#pragma unroll
        for (int nt = 0; nt < 4; nt++) {
            float* base = C + (size_t)(bm + warp_m * 64 + mt * 16 + er) * ODIM +
                          bn + warp_n * 32 + nt * 8 + ec;
            *reinterpret_cast<float2*>(base) =
                make_float2(acc[mt][nt][0], acc[mt][nt][1]);
            *reinterpret_cast<float2*>(base + 8 * ODIM) =
                make_float2(acc[mt][nt][2], acc[mt][nt][3]);
        }
    }
}

// ---------------------------------------------------------------------------
// LoRA shrink
// ---------------------------------------------------------------------------
__global__ void lora_shrink(const float* __restrict__ x,
                            const float* __restrict__ la,
                            const int*   __restrict__ idx) {
    const int t = blockIdx.x;
    const int l = idx[t];
    const float4* xt = reinterpret_cast<const float4*>(x + (size_t)t * DDIM);
    const float4* A  = reinterpret_cast<const float4*>(la + (size_t)l * RANK * DDIM);
    const int D4 = DDIM / 4;

    float acc[RANK];
#pragma unroll
    for (int r = 0; r < RANK; r++) acc[r] = 0.f;

    for (int i = threadIdx.x; i < D4; i += 128) {
        float4 xv = xt[i];
#pragma unroll
        for (int r = 0; r < RANK; r++) {
            float4 av = A[r * D4 + i];
            acc[r] += xv.x * av.x + xv.y * av.y + xv.z * av.z + xv.w * av.w;
        }
    }

    __shared__ float red[RANK][128];
#pragma unroll
    for (int r = 0; r < RANK; r++) red[r][threadIdx.x] = acc[r];
    __syncthreads();

    for (int off = 64; off > 0; off >>= 1) {
        if (threadIdx.x < off) {
#pragma unroll
            for (int r = 0; r < RANK; r++)
                red[r][threadIdx.x] += red[r][threadIdx.x + off];
        }
        __syncthreads();
    }
    if (threadIdx.x < RANK)
        g_s[t * RANK + threadIdx.x] = red[threadIdx.x][0];
}

// ---------------------------------------------------------------------------
// LoRA expand
// ---------------------------------------------------------------------------
__global__ void lora_expand(const float* __restrict__ lb,
                            const int*   __restrict__ idx,
                            float* __restrict__ out) {
    const int t = blockIdx.y;
    const int o = blockIdx.x * blockDim.x + threadIdx.x;

    __shared__ float ss[RANK];
    __shared__ int   sl;
    if (threadIdx.x < RANK) ss[threadIdx.x] = g_s[t * RANK + threadIdx.x];
    if (threadIdx.x == 0)   sl = idx[t];
    __syncthreads();

    const float4* Brow =
        reinterpret_cast<const float4*>(lb + ((size_t)sl * ODIM + o) * RANK);
    float acc = 0.f;
#pragma unroll
    for (int i = 0; i < 4; i++) {
        float4 b = Brow[i];
        acc += b.x * ss[4 * i + 0] + b.y * ss[4 * i + 1] +
               b.z * ss[4 * i + 2] + b.w * ss[4 * i + 3];
    }
    out[(size_t)t * ODIM + o] += acc;
}

// ---------------------------------------------------------------------------
// Launch: inputs order: x, weight, lora_a, lora_b, token_lora_idx
// ---------------------------------------------------------------------------
extern "C" void kernel_launch(void* const* d_in, const int* in_sizes, int n_in,
                              void* d_out, int out_size) {
    const float* x   = (const float*)d_in[0];
    const float* w   = (const float*)d_in[1];
    const float* la  = (const float*)d_in[2];
    const float* lb  = (const float*)d_in[3];
    const int*   idx = (const int*)d_in[4];
    float* out = (float*)d_out;

    cudaFuncSetAttribute(gemm_mma, cudaFuncAttributeMaxDynamicSharedMemorySize,
                         GEMM_SMEM);

    // 1) bf16 hi/lo splits
    split_x<<<1024, 256>>>(x);
    split_w<<<1024, 256>>>(w);

    // 2) LoRA shrink
    lora_shrink<<<T_TOK, 128>>>(x, la, idx);

    // 3) base GEMM on tensor cores (mma.sync)
    gemm_mma<<<(T_TOK / 128) * (ODIM / 128), 256, GEMM_SMEM>>>(out);

    // 4) LoRA expand
    lora_expand<<<dim3(ODIM / 256, T_TOK), 256>>>(lb, idx, out);
}

// round 4
// speedup vs baseline: 2.6702x; 1.0897x over previous
#include <cuda_runtime.h>
#include <cuda_bf16.h>
#include <cstdint>

// Problem constants
#define T_TOK 8192
#define DDIM  4096
#define ODIM  4096
#define LMAX  8
#define RANK  16

// ---------------------------------------------------------------------------
// Static device scratch (no allocations allowed)
// ---------------------------------------------------------------------------
__device__ float g_s[T_TOK * RANK];                      // LoRA shrink result
__device__ __nv_bfloat16 g_xhi[(size_t)T_TOK * DDIM];    // 64 MB
__device__ __nv_bfloat16 g_xlo[(size_t)T_TOK * DDIM];    // 64 MB
__device__ __nv_bfloat16 g_whi[(size_t)ODIM * DDIM];     // 32 MB
__device__ __nv_bfloat16 g_wlo[(size_t)ODIM * DDIM];     // 32 MB

// ---------------------------------------------------------------------------
// PTX helpers (sm_80/90-era: legal on plain sm_103 target)
// ---------------------------------------------------------------------------
__device__ __forceinline__ uint32_t smem_u32(const void* p) {
    uint32_t a;
    asm("{ .reg .u64 t; cvta.to.shared.u64 t, %1; cvt.u32.u64 %0, t; }"
        : "=r"(a) : "l"(p));
    return a;
}
__device__ __forceinline__ void cp16(uint32_t d, const void* g) {
    asm volatile("cp.async.cg.shared.global [%0], [%1], 16;"
                 :: "r"(d), "l"(g) : "memory");
}
__device__ __forceinline__ void ldsm4(uint32_t* r, uint32_t a) {
    asm volatile("ldmatrix.sync.aligned.m8n8.x4.shared.b16 {%0,%1,%2,%3}, [%4];"
                 : "=r"(r[0]), "=r"(r[1]), "=r"(r[2]), "=r"(r[3]) : "r"(a));
}
__device__ __forceinline__ void mma_bf16(float* c, const uint32_t* a,
                                         uint32_t b0, uint32_t b1) {
    asm volatile(
        "mma.sync.aligned.m16n8k16.row.col.f32.bf16.bf16.f32 "
        "{%0,%1,%2,%3}, {%4,%5,%6,%7}, {%8,%9}, {%0,%1,%2,%3};"
        : "+f"(c[0]), "+f"(c[1]), "+f"(c[2]), "+f"(c[3])
        : "r"(a[0]), "r"(a[1]), "r"(a[2]), "r"(a[3]), "r"(b0), "r"(b1));
}

// ---------------------------------------------------------------------------
// fp32 -> (hi, lo) bf16 split kernels
// ---------------------------------------------------------------------------
__global__ void split_x(const float* __restrict__ in) {
    size_t n4 = (size_t)T_TOK * DDIM / 4;
    const float4* in4 = reinterpret_cast<const float4*>(in);
    for (size_t i = blockIdx.x * blockDim.x + threadIdx.x; i < n4;
         i += (size_t)gridDim.x * blockDim.x) {
        float4 v = in4[i];
        __nv_bfloat16 h0 = __float2bfloat16(v.x), h1 = __float2bfloat16(v.y);
        __nv_bfloat16 h2 = __float2bfloat16(v.z), h3 = __float2bfloat16(v.w);
        __nv_bfloat162 hi0{h0, h1}, hi1{h2, h3};
        __nv_bfloat162 lo0{__float2bfloat16(v.x - __bfloat162float(h0)),
                           __float2bfloat16(v.y - __bfloat162float(h1))};
        __nv_bfloat162 lo1{__float2bfloat16(v.z - __bfloat162float(h2)),
                           __float2bfloat16(v.w - __bfloat162float(h3))};
        reinterpret_cast<__nv_bfloat162*>(g_xhi)[i * 2]     = hi0;
        reinterpret_cast<__nv_bfloat162*>(g_xhi)[i * 2 + 1] = hi1;
        reinterpret_cast<__nv_bfloat162*>(g_xlo)[i * 2]     = lo0;
        reinterpret_cast<__nv_bfloat162*>(g_xlo)[i * 2 + 1] = lo1;
    }
}
__global__ void split_w(const float* __restrict__ in) {
    size_t n4 = (size_t)ODIM * DDIM / 4;
    const float4* in4 = reinterpret_cast<const float4*>(in);
    for (size_t i = blockIdx.x * blockDim.x + threadIdx.x; i < n4;
         i += (size_t)gridDim.x * blockDim.x) {
        float4 v = in4[i];
        __nv_bfloat16 h0 = __float2bfloat16(v.x), h1 = __float2bfloat16(v.y);
        __nv_bfloat16 h2 = __float2bfloat16(v.z), h3 = __float2bfloat16(v.w);
        __nv_bfloat162 hi0{h0, h1}, hi1{h2, h3};
        __nv_bfloat162 lo0{__float2bfloat16(v.x - __bfloat162float(h0)),
                           __float2bfloat16(v.y - __bfloat162float(h1))};
        __nv_bfloat162 lo1{__float2bfloat16(v.z - __bfloat162float(h2)),
                           __float2bfloat16(v.w - __bfloat162float(h3))};
        reinterpret_cast<__nv_bfloat162*>(g_whi)[i * 2]     = hi0;
        reinterpret_cast<__nv_bfloat162*>(g_whi)[i * 2 + 1] = hi1;
        reinterpret_cast<__nv_bfloat162*>(g_wlo)[i * 2]     = lo0;
        reinterpret_cast<__nv_bfloat162*>(g_wlo)[i * 2 + 1] = lo1;
    }
}

// ---------------------------------------------------------------------------
// GEMM via mma.sync (bf16 x3 hi/lo products, fp32 accumulate)
// 128x256 CTA tile, BK=32, 3-stage cp.async pipeline, 8 warps (64x64 tiles).
// SMEM/stage: [Ahi(8K)|Alo(8K)|Bhi(16K)|Blo(16K)] = 48 KB, rows of 64B,
// 16B chunks XOR-swizzled: phys_chunk = c ^ ((row>>1)&3).
// ---------------------------------------------------------------------------
#define BKC     32
#define NCHUNKC (DDIM / BKC)
#define A_TILEB (128 * 64)
#define B_TILEB (256 * 64)
#define STAGEB  (2 * A_TILEB + 2 * B_TILEB)   // 48 KB
#define STAGES  3
#define GEMM_SMEM (STAGES * STAGEB)           // 144 KB

__global__ __launch_bounds__(256, 1)
void gemm_mma(float* __restrict__ C) {
    extern __shared__ char smem[];
    const uint32_t sb = smem_u32(smem);
    const int tid  = threadIdx.x;
    const int wid  = tid >> 5;
    const int lane = tid & 31;

    // Rasterize: GROUP_M=8 so a wave's working set stays L2-resident
    const int bid = blockIdx.x;
    const int TN = ODIM / 256;                 // 16
    const int GRP = 8;
    const int per = GRP * TN;                  // 128
    const int m_t = (bid / per) * GRP + (bid % per) % GRP;
    const int n_t = (bid % per) / GRP;
    const int bm = m_t * 128;
    const int bn = n_t * 256;

    const int warp_m = wid & 1;   // 2 x 64 rows
    const int warp_n = wid >> 1;  // 4 x 64 cols

    // -------- async loader: 12 x cp16 per thread per chunk --------
    auto issue_chunk = [&](int chunk, int stage) {
        const int k0 = chunk * BKC;
        const uint32_t sbase = sb + (uint32_t)stage * STAGEB;
#pragma unroll
        for (int t = 0; t < 2; t++) {           // Ahi, Alo
            const __nv_bfloat16* src = t ? g_xlo : g_xhi;
#pragma unroll
            for (int rep = 0; rep < 2; rep++) {
                const int idx = rep * 256 + tid;     // 0..511
                const int r = idx >> 2;              // 0..127
                const int c = idx & 3;
                const void* g = src + (size_t)(bm + r) * DDIM + k0 + c * 8;
                const uint32_t d = sbase + (uint32_t)t * A_TILEB + r * 64 +
                                   ((c ^ ((r >> 1) & 3)) << 4);
                cp16(d, g);
            }
        }
#pragma unroll
        for (int t = 0; t < 2; t++) {           // Bhi, Blo
            const __nv_bfloat16* src = t ? g_wlo : g_whi;
#pragma unroll
            for (int rep = 0; rep < 4; rep++) {
                const int idx = rep * 256 + tid;     // 0..1023
                const int r = idx >> 2;              // 0..255
                const int c = idx & 3;
                const void* g = src + (size_t)(bn + r) * DDIM + k0 + c * 8;
                const uint32_t d = sbase + 2 * A_TILEB + (uint32_t)t * B_TILEB +
                                   r * 64 + ((c ^ ((r >> 1) & 3)) << 4);
                cp16(d, g);
            }
        }
        asm volatile("cp.async.commit_group;" ::: "memory");
    };

    float acc[4][8][4];
#pragma unroll
    for (int i = 0; i < 4; i++)
#pragma unroll
        for (int j = 0; j < 8; j++)
#pragma unroll
            for (int q = 0; q < 4; q++) acc[i][j][q] = 0.f;

    // Prologue: fill STAGES-1 stages
#pragma unroll
    for (int s = 0; s < STAGES - 1; s++) issue_chunk(s, s);

    // A ldmatrix lane mapping: row = lane%16 (m), half = lane/16 (k-chunk)
    const int a_r = lane & 15;
    const int a_h = lane >> 4;
    // B ldmatrix lane mapping: row = (lane%8) + (lane/16)*8 (n), half = (lane>>3)&1
    const int b_r = (lane & 7) + ((lane >> 4) << 3);
    const int b_h = (lane >> 3) & 1;

    for (int i = 0; i < NCHUNKC; i++) {
        const int stage = i % STAGES;
        asm volatile("cp.async.wait_group %0;" :: "n"(STAGES - 2) : "memory");
        __syncthreads();
        if (i + STAGES - 1 < NCHUNKC)
            issue_chunk(i + STAGES - 1, (i + STAGES - 1) % STAGES);

        const uint32_t st = sb + (uint32_t)stage * STAGEB;
        const uint32_t Ah = st, Al = st + A_TILEB;
        const uint32_t Bh = st + 2 * A_TILEB, Bl = st + 2 * A_TILEB + B_TILEB;

#pragma unroll
        for (int ks = 0; ks < 2; ks++) {
            uint32_t ahi[4][4], alo[4][4], bhi[4][4], blo[4][4];
#pragma unroll
            for (int mt = 0; mt < 4; mt++) {
                const int row = warp_m * 64 + mt * 16 + a_r;
                const int cl = ks * 2 + a_h;
                const uint32_t off = row * 64 + ((cl ^ ((row >> 1) & 3)) << 4);
                ldsm4(ahi[mt], Ah + off);
                ldsm4(alo[mt], Al + off);
            }
#pragma unroll
            for (int p = 0; p < 4; p++) {
                const int row = warp_n * 64 + p * 16 + b_r;
                const int cl = ks * 2 + b_h;
                const uint32_t off = row * 64 + ((cl ^ ((row >> 1) & 3)) << 4);
                ldsm4(bhi[p], Bh + off);
                ldsm4(blo[p], Bl + off);
            }
            // Product-major ordering: same accumulator revisited only every
            // 32 independent MMAs -> no HMMA RAW stalls.
#pragma unroll
            for (int mt = 0; mt < 4; mt++)
#pragma unroll
                for (int nt = 0; nt < 8; nt++)
                    mma_bf16(acc[mt][nt], ahi[mt],
                             bhi[nt >> 1][(nt & 1) * 2], bhi[nt >> 1][(nt & 1) * 2 + 1]);
#pragma unroll
            for (int mt = 0; mt < 4; mt++)
#pragma unroll
                for (int nt = 0; nt < 8; nt++)
                    mma_bf16(acc[mt][nt], alo[mt],
                             bhi[nt >> 1][(nt & 1) * 2], bhi[nt >> 1][(nt & 1) * 2 + 1]);
#pragma unroll
            for (int mt = 0; mt < 4; mt++)
#pragma unroll
                for (int nt = 0; nt < 8; nt++)
                    mma_bf16(acc[mt][nt], ahi[mt],
                             blo[nt >> 1][(nt & 1) * 2], blo[nt >> 1][(nt & 1) * 2 + 1]);
        }
    }

    // Epilogue: c frag layout: rows lane/4 (+8), cols (lane%4)*2 (+1)
    const int er = lane >> 2;
    const int ec = (lane & 3) * 2;
#pragma unroll
    for (int mt = 0; mt < 4; mt++) {
#pragma unroll
        for (int nt = 0; nt < 8; nt++) {
            float* base = C + (size_t)(bm + warp_m * 64 + mt * 16 + er) * ODIM +
                          bn + warp_n * 64 + nt * 8 + ec;
            *reinterpret_cast<float2*>(base) =
                make_float2(acc[mt][nt][0], acc[mt][nt][1]);
            *reinterpret_cast<float2*>(base + 8 * ODIM) =
                make_float2(acc[mt][nt][2], acc[mt][nt][3]);
        }
    }
}

// ---------------------------------------------------------------------------
// LoRA shrink
// ---------------------------------------------------------------------------
__global__ void lora_shrink(const float* __restrict__ x,
                            const float* __restrict__ la,
                            const int*   __restrict__ idx) {
    const int t = blockIdx.x;
    const int l = idx[t];
    const float4* xt = reinterpret_cast<const float4*>(x + (size_t)t * DDIM);
    const float4* A  = reinterpret_cast<const float4*>(la + (size_t)l * RANK * DDIM);
    const int D4 = DDIM / 4;

    float acc[RANK];
#pragma unroll
    for (int r = 0; r < RANK; r++) acc[r] = 0.f;

    for (int i = threadIdx.x; i < D4; i += 128) {
        float4 xv = xt[i];
#pragma unroll
        for (int r = 0; r < RANK; r++) {
            float4 av = A[r * D4 + i];
            acc[r] += xv.x * av.x + xv.y * av.y + xv.z * av.z + xv.w * av.w;
        }
    }

    __shared__ float red[RANK][128];
#pragma unroll
    for (int r = 0; r < RANK; r++) red[r][threadIdx.x] = acc[r];
    __syncthreads();

    for (int off = 64; off > 0; off >>= 1) {
        if (threadIdx.x < off) {
#pragma unroll
            for (int r = 0; r < RANK; r++)
                red[r][threadIdx.x] += red[r][threadIdx.x + off];
        }
        __syncthreads();
    }
    if (threadIdx.x < RANK)
        g_s[t * RANK + threadIdx.x] = red[threadIdx.x][0];
}

// ---------------------------------------------------------------------------
// LoRA expand
// ---------------------------------------------------------------------------
__global__ void lora_expand(const float* __restrict__ lb,
                            const int*   __restrict__ idx,
                            float* __restrict__ out) {
    const int t = blockIdx.y;
    const int o = blockIdx.x * blockDim.x + threadIdx.x;

    __shared__ float ss[RANK];
    __shared__ int   sl;
    if (threadIdx.x < RANK) ss[threadIdx.x] = g_s[t * RANK + threadIdx.x];
    if (threadIdx.x == 0)   sl = idx[t];
    __syncthreads();

    const float4* Brow =
        reinterpret_cast<const float4*>(lb + ((size_t)sl * ODIM + o) * RANK);
    float acc = 0.f;
#pragma unroll
    for (int i = 0; i < 4; i++) {
        float4 b = Brow[i];
        acc += b.x * ss[4 * i + 0] + b.y * ss[4 * i + 1] +
               b.z * ss[4 * i + 2] + b.w * ss[4 * i + 3];
    }
    out[(size_t)t * ODIM + o] += acc;
}

// ---------------------------------------------------------------------------
// Launch: inputs order: x, weight, lora_a, lora_b, token_lora_idx
// ---------------------------------------------------------------------------
extern "C" void kernel_launch(void* const* d_in, const int* in_sizes, int n_in,
                              void* d_out, int out_size) {
    const float* x   = (const float*)d_in[0];
    const float* w   = (const float*)d_in[1];
    const float* la  = (const float*)d_in[2];
    const float* lb  = (const float*)d_in[3];
    const int*   idx = (const int*)d_in[4];
    float* out = (float*)d_out;

    cudaFuncSetAttribute(gemm_mma, cudaFuncAttributeMaxDynamicSharedMemorySize,
                         GEMM_SMEM);

    // 1) bf16 hi/lo splits
    split_x<<<1024, 256>>>(x);
    split_w<<<1024, 256>>>(w);

    // 2) LoRA shrink
    lora_shrink<<<T_TOK, 128>>>(x, la, idx);

    // 3) base GEMM on tensor cores (mma.sync)
    gemm_mma<<<(T_TOK / 128) * (ODIM / 256), 256, GEMM_SMEM>>>(out);

    // 4) LoRA expand
    lora_expand<<<dim3(ODIM / 256, T_TOK), 256>>>(lb, idx, out);
}

// round 5
// speedup vs baseline: 5.7082x; 2.1377x over previous
#include <cuda_runtime.h>
#include <cuda_fp16.h>
#include <cstdint>

// Problem constants
#define T_TOK 8192
#define DDIM  4096
#define ODIM  4096
#define LMAX  8
#define RANK  16

// ---------------------------------------------------------------------------
// Static device scratch (no allocations allowed)
// ---------------------------------------------------------------------------
__device__ float g_s[T_TOK * RANK];                // LoRA shrink result
__device__ __half g_xh[(size_t)T_TOK * DDIM];      // 64 MB
__device__ __half g_wh[(size_t)ODIM * DDIM];       // 32 MB

// ---------------------------------------------------------------------------
// PTX helpers (sm_80/90-era: legal on plain sm_103 target)
// ---------------------------------------------------------------------------
__device__ __forceinline__ uint32_t smem_u32(const void* p) {
    uint32_t a;
    asm("{ .reg .u64 t; cvta.to.shared.u64 t, %1; cvt.u32.u64 %0, t; }"
        : "=r"(a) : "l"(p));
    return a;
}
__device__ __forceinline__ void cp16(uint32_t d, const void* g) {
    asm volatile("cp.async.cg.shared.global [%0], [%1], 16;"
                 :: "r"(d), "l"(g) : "memory");
}
__device__ __forceinline__ void ldsm4(uint32_t* r, uint32_t a) {
    asm volatile("ldmatrix.sync.aligned.m8n8.x4.shared.b16 {%0,%1,%2,%3}, [%4];"
                 : "=r"(r[0]), "=r"(r[1]), "=r"(r[2]), "=r"(r[3]) : "r"(a));
}
__device__ __forceinline__ void mma_fp16(float* c, const uint32_t* a,
                                         uint32_t b0, uint32_t b1) {
    asm volatile(
        "mma.sync.aligned.m16n8k16.row.col.f32.f16.f16.f32 "
        "{%0,%1,%2,%3}, {%4,%5,%6,%7}, {%8,%9}, {%0,%1,%2,%3};"
        : "+f"(c[0]), "+f"(c[1]), "+f"(c[2]), "+f"(c[3])
        : "r"(a[0]), "r"(a[1]), "r"(a[2]), "r"(a[3]), "r"(b0), "r"(b1));
}

// ---------------------------------------------------------------------------
// fp32 -> fp16 conversion kernels
// ---------------------------------------------------------------------------
__global__ void conv_x(const float* __restrict__ in) {
    size_t n4 = (size_t)T_TOK * DDIM / 4;
    const float4* in4 = reinterpret_cast<const float4*>(in);
    for (size_t i = blockIdx.x * blockDim.x + threadIdx.x; i < n4;
         i += (size_t)gridDim.x * blockDim.x) {
        float4 v = in4[i];
        __half2 h0 = __floats2half2_rn(v.x, v.y);
        __half2 h1 = __floats2half2_rn(v.z, v.w);
        reinterpret_cast<__half2*>(g_xh)[i * 2]     = h0;
        reinterpret_cast<__half2*>(g_xh)[i * 2 + 1] = h1;
    }
}
__global__ void conv_w(const float* __restrict__ in) {
    size_t n4 = (size_t)ODIM * DDIM / 4;
    const float4* in4 = reinterpret_cast<const float4*>(in);
    for (size_t i = blockIdx.x * blockDim.x + threadIdx.x; i < n4;
         i += (size_t)gridDim.x * blockDim.x) {
        float4 v = in4[i];
        __half2 h0 = __floats2half2_rn(v.x, v.y);
        __half2 h1 = __floats2half2_rn(v.z, v.w);
        reinterpret_cast<__half2*>(g_wh)[i * 2]     = h0;
        reinterpret_cast<__half2*>(g_wh)[i * 2 + 1] = h1;
    }
}

// ---------------------------------------------------------------------------
// GEMM via mma.sync fp16 (single product, fp32 accumulate)
// 128x256 CTA tile, BK=64, 3-stage cp.async pipeline, 8 warps (64x64 tiles).
// SMEM/stage: A 128x128B (16K) + B 256x128B (32K) = 48 KB.
// Rows are 128 B = 8 x 16B chunks; swizzle: phys_chunk = c ^ (row & 7).
// ---------------------------------------------------------------------------
#define BKC     64
#define NCHUNKC (DDIM / BKC)
#define A_TILEB (128 * 128)
#define B_TILEB (256 * 128)
#define STAGEB  (A_TILEB + B_TILEB)           // 48 KB
#define STAGES  3
#define GEMM_SMEM (STAGES * STAGEB)           // 144 KB

__global__ __launch_bounds__(256, 1)
void gemm_mma(float* __restrict__ C) {
    extern __shared__ char smem[];
    const uint32_t sb = smem_u32(smem);
    const int tid  = threadIdx.x;
    const int wid  = tid >> 5;
    const int lane = tid & 31;

    // Rasterize: GROUP_M=8 so a wave's working set stays L2-resident
    const int bid = blockIdx.x;
    const int TN = ODIM / 256;                 // 16
    const int GRP = 8;
    const int per = GRP * TN;                  // 128
    const int m_t = (bid / per) * GRP + (bid % per) % GRP;
    const int n_t = (bid % per) / GRP;
    const int bm = m_t * 128;
    const int bn = n_t * 256;

    const int warp_m = wid & 1;   // 2 x 64 rows
    const int warp_n = wid >> 1;  // 4 x 64 cols

    // -------- async loader: 12 x cp16 per thread per chunk --------
    auto issue_chunk = [&](int chunk, int stage) {
        const int k0 = chunk * BKC;
        const uint32_t sbase = sb + (uint32_t)stage * STAGEB;
        // A: 128 rows x 8 chunks = 1024 cp16
#pragma unroll
        for (int rep = 0; rep < 4; rep++) {
            const int idx = rep * 256 + tid;     // 0..1023
            const int r = idx >> 3;              // 0..127
            const int c = idx & 7;
            const void* g = g_xh + (size_t)(bm + r) * DDIM + k0 + c * 8;
            const uint32_t d = sbase + r * 128 + ((c ^ (r & 7)) << 4);
            cp16(d, g);
        }
        // B: 256 rows x 8 chunks = 2048 cp16
#pragma unroll
        for (int rep = 0; rep < 8; rep++) {
            const int idx = rep * 256 + tid;     // 0..2047
            const int r = idx >> 3;              // 0..255
            const int c = idx & 7;
            const void* g = g_wh + (size_t)(bn + r) * DDIM + k0 + c * 8;
            const uint32_t d = sbase + A_TILEB + r * 128 + ((c ^ (r & 7)) << 4);
            cp16(d, g);
        }
        asm volatile("cp.async.commit_group;" ::: "memory");
    };

    float acc[4][8][4];
#pragma unroll
    for (int i = 0; i < 4; i++)
#pragma unroll
        for (int j = 0; j < 8; j++)
#pragma unroll
            for (int q = 0; q < 4; q++) acc[i][j][q] = 0.f;

    // Prologue: fill STAGES-1 stages
#pragma unroll
    for (int s = 0; s < STAGES - 1; s++) issue_chunk(s, s);

    // A ldmatrix lane mapping: row = lane%16 (m), half = lane/16 (k-chunk)
    const int a_r = lane & 15;
    const int a_h = lane >> 4;
    // B ldmatrix lane mapping: row = (lane%8) + (lane/16)*8 (n), half = (lane>>3)&1
    const int b_r = (lane & 7) + ((lane >> 4) << 3);
    const int b_h = (lane >> 3) & 1;

    for (int i = 0; i < NCHUNKC; i++) {
        const int stage = i % STAGES;
        asm volatile("cp.async.wait_group %0;" :: "n"(STAGES - 2) : "memory");
        __syncthreads();
        if (i + STAGES - 1 < NCHUNKC)
            issue_chunk(i + STAGES - 1, (i + STAGES - 1) % STAGES);

        const uint32_t Ab = sb + (uint32_t)stage * STAGEB;
        const uint32_t Bb = Ab + A_TILEB;

#pragma unroll
        for (int ks = 0; ks < 4; ks++) {          // 4 x k16 per chunk
            uint32_t af[4][4], bf[4][4];
#pragma unroll
            for (int mt = 0; mt < 4; mt++) {
                const int row = warp_m * 64 + mt * 16 + a_r;
                const int cl = ks * 2 + a_h;
                ldsm4(af[mt], Ab + row * 128 + ((cl ^ (row & 7)) << 4));
            }
#pragma unroll
            for (int p = 0; p < 4; p++) {
                const int row = warp_n * 64 + p * 16 + b_r;
                const int cl = ks * 2 + b_h;
                ldsm4(bf[p], Bb + row * 128 + ((cl ^ (row & 7)) << 4));
            }
#pragma unroll
            for (int mt = 0; mt < 4; mt++)
#pragma unroll
                for (int nt = 0; nt < 8; nt++)
                    mma_fp16(acc[mt][nt], af[mt],
                             bf[nt >> 1][(nt & 1) * 2], bf[nt >> 1][(nt & 1) * 2 + 1]);
        }
    }

    // Epilogue: c frag layout: rows lane/4 (+8), cols (lane%4)*2 (+1)
    const int er = lane >> 2;
    const int ec = (lane & 3) * 2;
#pragma unroll
    for (int mt = 0; mt < 4; mt++) {
#pragma unroll
        for (int nt = 0; nt < 8; nt++) {
            float* base = C + (size_t)(bm + warp_m * 64 + mt * 16 + er) * ODIM +
                          bn + warp_n * 64 + nt * 8 + ec;
            *reinterpret_cast<float2*>(base) =
                make_float2(acc[mt][nt][0], acc[mt][nt][1]);
            *reinterpret_cast<float2*>(base + 8 * ODIM) =
                make_float2(acc[mt][nt][2], acc[mt][nt][3]);
        }
    }
}

// ---------------------------------------------------------------------------
// LoRA shrink (fp32, exact)
// ---------------------------------------------------------------------------
__global__ void lora_shrink(const float* __restrict__ x,
                            const float* __restrict__ la,
                            const int*   __restrict__ idx) {
    const int t = blockIdx.x;
    const int l = idx[t];
    const float4* xt = reinterpret_cast<const float4*>(x + (size_t)t * DDIM);
    const float4* A  = reinterpret_cast<const float4*>(la + (size_t)l * RANK * DDIM);
    const int D4 = DDIM / 4;

    float acc[RANK];
#pragma unroll
    for (int r = 0; r < RANK; r++) acc[r] = 0.f;

    for (int i = threadIdx.x; i < D4; i += 128) {
        float4 xv = xt[i];
#pragma unroll
        for (int r = 0; r < RANK; r++) {
            float4 av = A[r * D4 + i];
            acc[r] += xv.x * av.x + xv.y * av.y + xv.z * av.z + xv.w * av.w;
        }
    }

    __shared__ float red[RANK][128];
#pragma unroll
    for (int r = 0; r < RANK; r++) red[r][threadIdx.x] = acc[r];
    __syncthreads();

    for (int off = 64; off > 0; off >>= 1) {
        if (threadIdx.x < off) {
#pragma unroll
            for (int r = 0; r < RANK; r++)
                red[r][threadIdx.x] += red[r][threadIdx.x + off];
        }
        __syncthreads();
    }
    if (threadIdx.x < RANK)
        g_s[t * RANK + threadIdx.x] = red[threadIdx.x][0];
}

// ---------------------------------------------------------------------------
// LoRA expand (fp32, exact)
// ---------------------------------------------------------------------------
__global__ void lora_expand(const float* __restrict__ lb,
                            const int*   __restrict__ idx,
                            float* __restrict__ out) {
    const int t = blockIdx.y;
    const int o = blockIdx.x * blockDim.x + threadIdx.x;

    __shared__ float ss[RANK];
    __shared__ int   sl;
    if (threadIdx.x < RANK) ss[threadIdx.x] = g_s[t * RANK + threadIdx.x];
    if (threadIdx.x == 0)   sl = idx[t];
    __syncthreads();

    const float4* Brow =
        reinterpret_cast<const float4*>(lb + ((size_t)sl * ODIM + o) * RANK);
    float acc = 0.f;
#pragma unroll
    for (int i = 0; i < 4; i++) {
        float4 b = Brow[i];
        acc += b.x * ss[4 * i + 0] + b.y * ss[4 * i + 1] +
               b.z * ss[4 * i + 2] + b.w * ss[4 * i + 3];
    }
    out[(size_t)t * ODIM + o] += acc;
}

// ---------------------------------------------------------------------------
// Launch: inputs order: x, weight, lora_a, lora_b, token_lora_idx
// ---------------------------------------------------------------------------
extern "C" void kernel_launch(void* const* d_in, const int* in_sizes, int n_in,
                              void* d_out, int out_size) {
    const float* x   = (const float*)d_in[0];
    const float* w   = (const float*)d_in[1];
    const float* la  = (const float*)d_in[2];
    const float* lb  = (const float*)d_in[3];
    const int*   idx = (const int*)d_in[4];
    float* out = (float*)d_out;

    cudaFuncSetAttribute(gemm_mma, cudaFuncAttributeMaxDynamicSharedMemorySize,
                         GEMM_SMEM);

    // 1) fp16 conversions
    conv_x<<<1024, 256>>>(x);
    conv_w<<<1024, 256>>>(w);

    // 2) LoRA shrink
    lora_shrink<<<T_TOK, 128>>>(x, la, idx);

    // 3) base GEMM on tensor cores (fp16 mma.sync, fp32 accumulate)
    gemm_mma<<<(T_TOK / 128) * (ODIM / 256), 256, GEMM_SMEM>>>(out);

    // 4) LoRA expand
    lora_expand<<<dim3(ODIM / 256, T_TOK), 256>>>(lb, idx, out);
}

// round 6
// speedup vs baseline: 6.6986x; 1.1735x over previous
#include <cuda_runtime.h>
#include <cuda_fp16.h>
#include <cstdint>

// Problem constants
#define T_TOK 8192
#define DDIM  4096
#define ODIM  4096
#define LMAX  8
#define RANK  16
#define KEXT  (LMAX * RANK)     // 128 extension columns
#define KTOT  (DDIM + KEXT)     // 4224

// ---------------------------------------------------------------------------
// Static device scratch (no allocations allowed)
// ---------------------------------------------------------------------------
__device__ __half g_xh[(size_t)T_TOK * DDIM];      // x  in fp16 (64 MB)
__device__ __half g_wh[(size_t)ODIM * DDIM];       // W  in fp16 (32 MB)
__device__ __half g_xe[(size_t)T_TOK * KEXT];      // S~ one-hot shrink (2 MB)
__device__ __half g_we[(size_t)ODIM * KEXT];       // B_cat (1 MB)
__device__ int    g_cnt[LMAX];                     // per-adapter token counts
__device__ int    g_tok[LMAX * T_TOK];             // per-adapter token lists

// ---------------------------------------------------------------------------
// PTX helpers (sm_80/90-era: legal on plain sm_103 target)
// ---------------------------------------------------------------------------
__device__ __forceinline__ uint32_t smem_u32(const void* p) {
    uint32_t a;
    asm("{ .reg .u64 t; cvta.to.shared.u64 t, %1; cvt.u32.u64 %0, t; }"
        : "=r"(a) : "l"(p));
    return a;
}
__device__ __forceinline__ void cp16(uint32_t d, const void* g) {
    asm volatile("cp.async.cg.shared.global [%0], [%1], 16;"
                 :: "r"(d), "l"(g) : "memory");
}
__device__ __forceinline__ void ldsm4(uint32_t* r, uint32_t a) {
    asm volatile("ldmatrix.sync.aligned.m8n8.x4.shared.b16 {%0,%1,%2,%3}, [%4];"
                 : "=r"(r[0]), "=r"(r[1]), "=r"(r[2]), "=r"(r[3]) : "r"(a));
}
__device__ __forceinline__ void mma_fp16(float* c, const uint32_t* a,
                                         uint32_t b0, uint32_t b1) {
    asm volatile(
        "mma.sync.aligned.m16n8k16.row.col.f32.f16.f16.f32 "
        "{%0,%1,%2,%3}, {%4,%5,%6,%7}, {%8,%9}, {%0,%1,%2,%3};"
        : "+f"(c[0]), "+f"(c[1]), "+f"(c[2]), "+f"(c[3])
        : "r"(a[0]), "r"(a[1]), "r"(a[2]), "r"(a[3]), "r"(b0), "r"(b1));
}

// ---------------------------------------------------------------------------
// Conversions
// ---------------------------------------------------------------------------
__global__ void conv_x(const float* __restrict__ in) {
    size_t n4 = (size_t)T_TOK * DDIM / 4;
    const float4* in4 = reinterpret_cast<const float4*>(in);
    for (size_t i = blockIdx.x * blockDim.x + threadIdx.x; i < n4;
         i += (size_t)gridDim.x * blockDim.x) {
        float4 v = in4[i];
        reinterpret_cast<__half2*>(g_xh)[i * 2]     = __floats2half2_rn(v.x, v.y);
        reinterpret_cast<__half2*>(g_xh)[i * 2 + 1] = __floats2half2_rn(v.z, v.w);
    }
}
__global__ void conv_w(const float* __restrict__ in) {
    size_t n4 = (size_t)ODIM * DDIM / 4;
    const float4* in4 = reinterpret_cast<const float4*>(in);
    for (size_t i = blockIdx.x * blockDim.x + threadIdx.x; i < n4;
         i += (size_t)gridDim.x * blockDim.x) {
        float4 v = in4[i];
        reinterpret_cast<__half2*>(g_wh)[i * 2]     = __floats2half2_rn(v.x, v.y);
        reinterpret_cast<__half2*>(g_wh)[i * 2 + 1] = __floats2half2_rn(v.z, v.w);
    }
}
// B_cat: g_we[o, l*16+r] = lora_b[l, o, r]
__global__ void conv_we(const float* __restrict__ lb) {
    const int i = blockIdx.x * blockDim.x + threadIdx.x;   // over ODIM*LMAX
    if (i >= ODIM * LMAX) return;
    const int o = i >> 3;
    const int l = i & 7;
    const float4* src = reinterpret_cast<const float4*>(lb + ((size_t)l * ODIM + o) * RANK);
    __half2 h[8];
#pragma unroll
    for (int q = 0; q < 4; q++) {
        float4 v = src[q];
        h[q * 2]     = __floats2half2_rn(v.x, v.y);
        h[q * 2 + 1] = __floats2half2_rn(v.z, v.w);
    }
    __half2* dst = reinterpret_cast<__half2*>(g_we + (size_t)o * KEXT + l * RANK);
    *reinterpret_cast<uint4*>(dst)     = *reinterpret_cast<uint4*>(h);
    *reinterpret_cast<uint4*>(dst + 4) = *reinterpret_cast<uint4*>(h + 4);
}

// ---------------------------------------------------------------------------
// Token bucketing by adapter (re-zeroed every launch; output deterministic
// because each token's row is computed independently of list order)
// ---------------------------------------------------------------------------
__global__ void zero_cnt() { if (threadIdx.x < LMAX) g_cnt[threadIdx.x] = 0; }
__global__ void build_lists(const int* __restrict__ idx) {
    const int t = blockIdx.x * blockDim.x + threadIdx.x;
    if (t < T_TOK) {
        const int l = idx[t];
        const int p = atomicAdd(&g_cnt[l], 1);
        g_tok[l * T_TOK + p] = t;
    }
}

// ---------------------------------------------------------------------------
// Adapter-grouped LoRA shrink -> one-hot fp16 rows g_xe[t, :].
// Block = (adapter l, group of 64 tokens). A_l chunk staged in SMEM (fp32).
// Thread (ti, ds): token ti, d-slices {16j + 4ds}; 16 fp32 accumulators.
// ---------------------------------------------------------------------------
__global__ __launch_bounds__(256, 1)
void shrink_grouped(const float* __restrict__ la) {
    const int l = blockIdx.x;
    const int start = blockIdx.y * 64;
    const int cnt = g_cnt[l];
    if (start >= cnt) return;
    const int tid = threadIdx.x;
    const int ti = tid >> 2;
    const int ds = tid & 3;

    __shared__ float Asm[RANK][512];
    __shared__ int toks[64];
    if (tid < 64)
        toks[tid] = (start + tid < cnt) ? g_tok[l * T_TOK + start + tid] : -1;
    __syncthreads();
    const int t = toks[ti];

    float acc[RANK];
#pragma unroll
    for (int r = 0; r < RANK; r++) acc[r] = 0.f;

    for (int ch = 0; ch < DDIM / 512; ch++) {
        const float* Ab = la + (size_t)l * RANK * DDIM + ch * 512;
#pragma unroll
        for (int it = 0; it < 8; it++) {              // 2048 float4 loads
            const int i = it * 256 + tid;
            const int r = i >> 7;
            const int c4 = i & 127;
            reinterpret_cast<float4*>(&Asm[r][0])[c4] =
                reinterpret_cast<const float4*>(Ab + (size_t)r * DDIM)[c4];
        }
        __syncthreads();
        if (t >= 0) {
            const __half2* xr = reinterpret_cast<const __half2*>(
                g_xh + (size_t)t * DDIM + ch * 512);
#pragma unroll
            for (int j = 0; j < 32; j++) {
                const int d = j * 16 + ds * 4;
                float2 x01 = __half22float2(xr[d >> 1]);
                float2 x23 = __half22float2(xr[(d >> 1) + 1]);
#pragma unroll
                for (int r = 0; r < RANK; r++) {
                    float4 a = *reinterpret_cast<const float4*>(&Asm[r][d]);
                    acc[r] += x01.x * a.x + x01.y * a.y + x23.x * a.z + x23.y * a.w;
                }
            }
        }
        __syncthreads();
    }

    // Reduce across the 4 d-slice threads (consecutive lanes)
#pragma unroll
    for (int r = 0; r < RANK; r++) {
        acc[r] += __shfl_xor_sync(0xffffffffu, acc[r], 1);
        acc[r] += __shfl_xor_sync(0xffffffffu, acc[r], 2);
    }
    if (ds == 0 && t >= 0) {
        __half2* row = reinterpret_cast<__half2*>(g_xe + (size_t)t * KEXT);
        const int c0 = l * (RANK / 2);                 // first half2 col of this adapter
#pragma unroll
        for (int c = 0; c < KEXT / 2; c++) {
            __half2 v = __floats2half2_rn(0.f, 0.f);
            if (c >= c0 && c < c0 + RANK / 2)
                v = __floats2half2_rn(acc[(c - c0) * 2], acc[(c - c0) * 2 + 1]);
            row[c] = v;
        }
    }
}

// ---------------------------------------------------------------------------
// Fused GEMM: out = [x | S~] @ [W | B_cat]^T   (fp16 mma.sync, fp32 accum)
// 128x256 CTA tile, BK=64, 4-stage cp.async pipeline (192 KB SMEM), 8 warps.
// Rows 128 B = 8 x 16B chunks, swizzle phys_chunk = c ^ (row & 7).
// ---------------------------------------------------------------------------
#define BKC     64
#define NCHUNKC (KTOT / BKC)                  // 66
#define A_TILEB (128 * 128)
#define B_TILEB (256 * 128)
#define STAGEB  (A_TILEB + B_TILEB)           // 48 KB
#define STAGES  4
#define GEMM_SMEM (STAGES * STAGEB)           // 192 KB

__global__ __launch_bounds__(256, 1)
void gemm_mma(float* __restrict__ C) {
    extern __shared__ char smem[];
    const uint32_t sb = smem_u32(smem);
    const int tid  = threadIdx.x;
    const int wid  = tid >> 5;
    const int lane = tid & 31;

    const int bid = blockIdx.x;
    const int TN = ODIM / 256;                 // 16
    const int GRP = 8;
    const int per = GRP * TN;                  // 128
    const int m_t = (bid / per) * GRP + (bid % per) % GRP;
    const int n_t = (bid % per) / GRP;
    const int bm = m_t * 128;
    const int bn = n_t * 256;

    const int warp_m = wid & 1;
    const int warp_n = wid >> 1;

    auto issue_chunk = [&](int chunk, int stage) {
        const int k0 = chunk * BKC;
        const bool ext = (k0 >= DDIM);
        const __half* asrc = ext ? g_xe : g_xh;
        const __half* bsrc = ext ? g_we : g_wh;
        const size_t astr = ext ? KEXT : DDIM;
        const int ak = ext ? (k0 - DDIM) : k0;
        const uint32_t sbase = sb + (uint32_t)stage * STAGEB;
#pragma unroll
        for (int rep = 0; rep < 4; rep++) {            // A: 1024 cp16
            const int idx = rep * 256 + tid;
            const int r = idx >> 3;
            const int c = idx & 7;
            const void* g = asrc + (size_t)(bm + r) * astr + ak + c * 8;
            cp16(sbase + r * 128 + ((c ^ (r & 7)) << 4), g);
        }
#pragma unroll
        for (int rep = 0; rep < 8; rep++) {            // B: 2048 cp16
            const int idx = rep * 256 + tid;
            const int r = idx >> 3;
            const int c = idx & 7;
            const void* g = bsrc + (size_t)(bn + r) * astr + ak + c * 8;
            cp16(sbase + A_TILEB + r * 128 + ((c ^ (r & 7)) << 4), g);
        }
        asm volatile("cp.async.commit_group;" ::: "memory");
    };

    float acc[4][8][4];
#pragma unroll
    for (int i = 0; i < 4; i++)
#pragma unroll
        for (int j = 0; j < 8; j++)
#pragma unroll
            for (int q = 0; q < 4; q++) acc[i][j][q] = 0.f;

#pragma unroll
    for (int s = 0; s < STAGES - 1; s++) issue_chunk(s, s);

    const int a_r = lane & 15;
    const int a_h = lane >> 4;
    const int b_r = (lane & 7) + ((lane >> 4) << 3);
    const int b_h = (lane >> 3) & 1;

    for (int i = 0; i < NCHUNKC; i++) {
        const int stage = i % STAGES;
        asm volatile("cp.async.wait_group %0;" :: "n"(STAGES - 2) : "memory");
        __syncthreads();
        if (i + STAGES - 1 < NCHUNKC)
            issue_chunk(i + STAGES - 1, (i + STAGES - 1) % STAGES);

        const uint32_t Ab = sb + (uint32_t)stage * STAGEB;
        const uint32_t Bb = Ab + A_TILEB;

#pragma unroll
        for (int ks = 0; ks < 4; ks++) {
            uint32_t af[4][4], bf[4][4];
#pragma unroll
            for (int mt = 0; mt < 4; mt++) {
                const int row = warp_m * 64 + mt * 16 + a_r;
                const int cl = ks * 2 + a_h;
                ldsm4(af[mt], Ab + row * 128 + ((cl ^ (row & 7)) << 4));
            }
#pragma unroll
            for (int p = 0; p < 4; p++) {
                const int row = warp_n * 64 + p * 16 + b_r;
                const int cl = ks * 2 + b_h;
                ldsm4(bf[p], Bb + row * 128 + ((cl ^ (row & 7)) << 4));
            }
#pragma unroll
            for (int mt = 0; mt < 4; mt++)
#pragma unroll
                for (int nt = 0; nt < 8; nt++)
                    mma_fp16(acc[mt][nt], af[mt],
                             bf[nt >> 1][(nt & 1) * 2], bf[nt >> 1][(nt & 1) * 2 + 1]);
        }
    }

    const int er = lane >> 2;
    const int ec = (lane & 3) * 2;
#pragma unroll
    for (int mt = 0; mt < 4; mt++) {
#pragma unroll
        for (int nt = 0; nt < 8; nt++) {
            float* base = C + (size_t)(bm + warp_m * 64 + mt * 16 + er) * ODIM +
                          bn + warp_n * 64 + nt * 8 + ec;
            *reinterpret_cast<float2*>(base) =
                make_float2(acc[mt][nt][0], acc[mt][nt][1]);
            *reinterpret_cast<float2*>(base + 8 * ODIM) =
                make_float2(acc[mt][nt][2], acc[mt][nt][3]);
        }
    }
}

// ---------------------------------------------------------------------------
// Launch: inputs order: x, weight, lora_a, lora_b, token_lora_idx
// ---------------------------------------------------------------------------
extern "C" void kernel_launch(void* const* d_in, const int* in_sizes, int n_in,
                              void* d_out, int out_size) {
    const float* x   = (const float*)d_in[0];
    const float* w   = (const float*)d_in[1];
    const float* la  = (const float*)d_in[2];
    const float* lb  = (const float*)d_in[3];
    const int*   idx = (const int*)d_in[4];
    float* out = (float*)d_out;

    cudaFuncSetAttribute(gemm_mma, cudaFuncAttributeMaxDynamicSharedMemorySize,
                         GEMM_SMEM);

    conv_x<<<1024, 256>>>(x);
    conv_w<<<1024, 256>>>(w);
    conv_we<<<(ODIM * LMAX + 255) / 256, 256>>>(lb);

    zero_cnt<<<1, 32>>>();
    build_lists<<<T_TOK / 256, 256>>>(idx);
    shrink_grouped<<<dim3(LMAX, T_TOK / 64), 256>>>(la);

    gemm_mma<<<(T_TOK / 128) * (ODIM / 256), 256, GEMM_SMEM>>>(out);
}